// round 17
// baseline (speedup 1.0000x reference)
#include <cuda_runtime.h>
#include <cstdint>

#define S_DIM 384

// fp16 fragment-layout operand buffers (packed half2 words, written by kernel 1):
// g_Ah: [MI=m/16 (768)][kf2=k/16 (32)][128 w]  A-frag m16n8k16 (m=i*32+c, k=n)
// g_Bh: [NI=p/8 (1536)][kf2 (32)][64 w]        B-frag            (p=j*32+d)
// g_Wh: [zg=zz/16 (8)][kf2'=k'/16 (64)][128 w] A-frag for W, k' = c*32+d (= k identity)
__device__ unsigned int g_Ah[768 * 32 * 128];
__device__ unsigned int g_Bh[1536 * 32 * 64];
__device__ unsigned int g_Wh[8 * 64 * 128];

// ---------------------------------------------------------------- helpers
__device__ __forceinline__ uint32_t smem_u32(const void* p) {
    uint32_t a;
    asm("{ .reg .u64 t; cvta.to.shared.u64 t, %1; cvt.u32.u64 %0, t; }" : "=r"(a) : "l"(p));
    return a;
}
__device__ __forceinline__ uint32_t pack_h2(float lo, float hi) {
    uint32_t u;
    asm("cvt.rn.f16x2.f32 %0, %1, %2;" : "=r"(u) : "f"(hi), "f"(lo));
    return u;
}
__device__ __forceinline__ void lds128(uint32_t* v, uint32_t a) {
    asm volatile("ld.shared.v4.b32 {%0,%1,%2,%3}, [%4];"
                 : "=r"(v[0]), "=r"(v[1]), "=r"(v[2]), "=r"(v[3]) : "r"(a));
}
__device__ __forceinline__ void lds64(uint32_t* v, uint32_t a) {
    asm volatile("ld.shared.v2.b32 {%0,%1}, [%2];"
                 : "=r"(v[0]), "=r"(v[1]) : "r"(a));
}
__device__ __forceinline__ uint32_t lds32w(uint32_t a) {
    uint32_t v; asm volatile("ld.shared.b32 %0, [%1];" : "=r"(v) : "r"(a)); return v;
}
__device__ __forceinline__ void sts32(uint32_t a, uint32_t v) {
    asm volatile("st.shared.b32 [%0], %1;" :: "r"(a), "r"(v) : "memory");
}
__device__ __forceinline__ void sts32f(uint32_t a, float v) {
    asm volatile("st.shared.b32 [%0], %1;" :: "r"(a), "f"(v) : "memory");
}
__device__ __forceinline__ void sts16f(uint32_t a, float v) {
    asm volatile("{ .reg .b16 h; cvt.rn.f16.f32 h, %1; st.shared.b16 [%0], h; }"
                 :: "r"(a), "f"(v) : "memory");
}
__device__ __forceinline__ void cp16(uint32_t dst, const void* src) {
    asm volatile("cp.async.cg.shared.global [%0], [%1], 16;" :: "r"(dst), "l"(src));
}
#define CP_COMMIT() asm volatile("cp.async.commit_group;" ::: "memory")
#define CP_WAIT2()  asm volatile("cp.async.wait_group 2;" ::: "memory")
#define CP_WAIT1()  asm volatile("cp.async.wait_group 1;" ::: "memory")
#define CP_WAIT0()  asm volatile("cp.async.wait_group 0;" ::: "memory")

// m16n8k16 fp16 MMA, f32 accum: D += A*B
__device__ __forceinline__ void mma16(float* d, const uint32_t* a, uint32_t b0, uint32_t b1) {
    asm volatile(
        "mma.sync.aligned.m16n8k16.row.col.f32.f16.f16.f32 "
        "{%0,%1,%2,%3}, {%4,%5,%6,%7}, {%8,%9}, {%0,%1,%2,%3};"
        : "+f"(d[0]), "+f"(d[1]), "+f"(d[2]), "+f"(d[3])
        : "r"(a[0]), "r"(a[1]), "r"(a[2]), "r"(a[3]), "r"(b0), "r"(b1));
}

// ---------------------------------------------------------------- kernel 1 (R15, unchanged)
__global__ __launch_bounds__(256) void ln_proj_kernel(
    const float* __restrict__ m_si, const float* __restrict__ ln_g,
    const float* __restrict__ ln_b, const float* __restrict__ w_ab,
    const float* __restrict__ w_final)
{
    __shared__ unsigned short mn_s[64 * 36];
    __shared__ float a_s[32 * 66];
    __shared__ float b_s[32 * 66];

    int t = threadIdx.x, warp = t >> 5, lane = t & 31;
    int g = lane >> 2, r = lane & 3;
    int b = blockIdx.x;
    int s = b >> 3, n0 = (b & 7) * 64;

    if (b < 256) {
        int i = b * 256 + t;
        int zg = i >> 13, kf2 = (i >> 7) & 63, waddr = i & 127;
        int wl = waddr >> 2, wi = waddr & 3;
        int zz = zg * 16 + (wi & 1) * 8 + (wl >> 2);
        int k0 = kf2 * 16 + ((wi >> 1) & 1) * 8 + (wl & 3) * 2;
        g_Wh[i] = pack_h2(w_final[zz * 1024 + k0], w_final[zz * 1024 + k0 + 1]);
    }

    uint32_t awf[4][2][4];
    #pragma unroll
    for (int mi = 0; mi < 4; mi++)
        #pragma unroll
        for (int ki = 0; ki < 2; ki++)
            #pragma unroll
            for (int wi = 0; wi < 4; wi++) {
                int d = mi * 16 + (wi & 1) * 8 + g;
                int k = ki * 16 + ((wi >> 1) & 1) * 8 + 2 * r;
                float2 wv = *reinterpret_cast<const float2*>(w_ab + d * 32 + k);
                awf[mi][ki][wi] = pack_h2(wv.x, wv.y);
            }

    uint32_t mnb = smem_u32(mn_s);
    float gg = ln_g[lane], bb = ln_b[lane];

    #pragma unroll
    for (int it = 0; it < 8; it++) {
        int nl = warp * 8 + it;
        float x = m_si[((size_t)(s * 512 + n0 + nl)) * 32 + lane];
        float sum = x;
        #pragma unroll
        for (int o = 16; o; o >>= 1) sum += __shfl_xor_sync(0xFFFFFFFFu, sum, o);
        float mu = sum * (1.0f / 32.0f);
        float dx = x - mu;
        float v = dx * dx;
        #pragma unroll
        for (int o = 16; o; o >>= 1) v += __shfl_xor_sync(0xFFFFFFFFu, v, o);
        float mn = dx * rsqrtf(v * (1.0f / 32.0f) + 1e-5f) * gg + bb;
        sts16f(mnb + (uint32_t)(nl * 36 + lane) * 2u, mn);
    }
    __syncwarp();

    float acc[4][4];
    #pragma unroll
    for (int mi = 0; mi < 4; mi++)
        #pragma unroll
        for (int cc = 0; cc < 4; cc++) acc[mi][cc] = 0.0f;

    #pragma unroll
    for (int ki = 0; ki < 2; ki++) {
        uint32_t rowb = mnb + (uint32_t)((warp * 8 + g) * 18 + ki * 8 + r) * 4u;
        uint32_t b0 = lds32w(rowb);
        uint32_t b1 = lds32w(rowb + 16u);
        #pragma unroll
        for (int mi = 0; mi < 4; mi++)
            mma16(acc[mi], awf[mi][ki], b0, b1);
    }

    uint32_t asb = smem_u32(a_s), bsb = smem_u32(b_s);
    #pragma unroll
    for (int mi = 0; mi < 4; mi++)
        #pragma unroll
        for (int cc = 0; cc < 4; cc++) {
            int d = mi * 16 + ((cc & 2) ? 8 : 0) + g;
            int nl = warp * 8 + 2 * r + (cc & 1);
            uint32_t base = (d < 32) ? asb : bsb;
            sts32f(base + (uint32_t)((d & 31) * 66 + nl) * 4u, acc[mi][cc]);
        }
    __syncthreads();

    int kf0 = n0 >> 4;

    {
        int wb = t * 4;
        int MIl = wb >> 9, rem = wb & 511;
        int kf2l = rem >> 7, waddr = rem & 127;
        int wl = waddr >> 2;
        uint4 v;
        uint32_t* vp = &v.x;
        #pragma unroll
        for (int wi = 0; wi < 4; wi++) {
            int c  = MIl * 16 + (wi & 1) * 8 + (wl >> 2);
            int nl = kf2l * 16 + ((wi >> 1) & 1) * 8 + (wl & 3) * 2;
            vp[wi] = pack_h2(a_s[c * 66 + nl], a_s[c * 66 + nl + 1]);
        }
        *reinterpret_cast<uint4*>(
            g_Ah + ((size_t)(s * 2 + MIl) * 32 + kf0 + kf2l) * 128 + waddr) = v;
    }
    {
        int wb = t * 4;
        int NIl = wb >> 8, rem = wb & 255;
        int kf2l = rem >> 6, waddr = rem & 63;
        uint4 v;
        uint32_t* vp = &v.x;
        #pragma unroll
        for (int e = 0; e < 4; e++) {
            int wd = waddr + e;
            int wl = wd >> 1, wi = wd & 1;
            int d_row = NIl * 8 + (wl >> 2);
            int nl = kf2l * 16 + wi * 8 + (wl & 3) * 2;
            vp[e] = pack_h2(b_s[d_row * 66 + nl], b_s[d_row * 66 + nl + 1]);
        }
        *reinterpret_cast<uint4*>(
            g_Bh + ((size_t)(s * 4 + NIl) * 32 + kf0 + kf2l) * 64 + waddr) = v;
    }
}

// ---------------------------------------------------------------- kernel 2
// 256 threads, 8 warps (2m x 4p), warp tile 64x32. CTA: 128(m) x 256(p) via
// TWO sequential 128x128 phases sharing one W-epilogue (32 pairs).
// SMEM: osm [rows 256][264B] = 67584 at 0 (row = kf2p + (m>>5)*64).
//   Mainloop stages: 4 x 8KB at 67584 (k=16 chunks).  W stage (epilogue):
//   per-warp 2-buf of 2KB at 67584 + w*4096 + buf*2048.
// SMEM2 = 100352 -> 2 CTAs/SM, 16 warps/SM.
#define OFF_ST  67584u
#define STG     8192u
#define SMEM2   100352

__device__ __forceinline__ void load_AB(uint32_t slot, int ch, int mi0, int ni0, int t) {
    // A: 256 16B units [MIi 8][unit 32]
    cp16(slot + (uint32_t)t * 16u,
         g_Ah + ((size_t)(mi0 + (t >> 5)) * 32 + ch) * 128 + (t & 31) * 4);
    // B: 256 units [NIl 16][unit 16]
    cp16(slot + 4096u + (uint32_t)t * 16u,
         g_Bh + ((size_t)(ni0 + (t >> 4)) * 32 + ch) * 64 + (t & 15) * 4);
}

// W stage per chunk (k'=64): [ks 4][512B] = 2KB per warp buffer (zg = w).
__device__ __forceinline__ void load_Wc(uint32_t sb, int ch, int buf, int w, int lane) {
    uint32_t wsb = sb + OFF_ST + (uint32_t)w * 4096u + (buf ? 2048u : 0u);
    #pragma unroll
    for (int q = 0; q < 4; q++) {
        int idx = lane + q * 32;                  // 0..127 16B units
        cp16(wsb + (uint32_t)idx * 16u,
             g_Wh + ((size_t)w * 64 + ch * 4 + (idx >> 5)) * 128 + (idx & 31) * 4);
    }
}

__global__ __launch_bounds__(256, 2) void opm_mma_kernel(
    const float* __restrict__ b_final, float* __restrict__ z)
{
    extern __shared__ char smem_raw[];
    uint32_t sb = smem_u32(smem_raw);

    int t = threadIdx.x, w = t >> 5, lane = t & 31;
    int g = lane >> 2, r = lane & 3;
    int wm = w >> 2, wn = w & 3;                 // 2(m) x 4(p) warps, 64x32 tiles
    int mi0 = blockIdx.y * 8;
    int nib = blockIdx.x * 32;                   // NI base (8 j per CTA)
    uint32_t l16 = (uint32_t)lane * 16u, l8 = (uint32_t)lane * 8u;

    // initial preload: phase-0 chunks 0..2
    load_AB(sb + OFF_ST + 0u * STG, 0, mi0, nib, t); CP_COMMIT();
    load_AB(sb + OFF_ST + 1u * STG, 1, mi0, nib, t); CP_COMMIT();
    load_AB(sb + OFF_ST + 2u * STG, 2, mi0, nib, t); CP_COMMIT();

    const float sc = 1.0f / 512.0f;

    #pragma unroll 1
    for (int ph = 0; ph < 2; ph++) {
        int ni0 = nib + ph * 16;

        float acc[4][4][4];
        #pragma unroll
        for (int i = 0; i < 4; i++)
            #pragma unroll
            for (int j = 0; j < 4; j++)
                #pragma unroll
                for (int cc = 0; cc < 4; cc++) acc[i][j][cc] = 0.0f;

        // ---- mainloop: 32 chunks of k=16, 4-stage ring
        for (int s = 0; s < 32; s++) {
            if (s <= 29) CP_WAIT2();
            else if (s == 30) CP_WAIT1();
            else CP_WAIT0();
            __syncthreads();

            uint32_t slot = sb + OFF_ST + (uint32_t)(s & 3) * STG;

            uint32_t bfr[4][2];
            #pragma unroll
            for (int j = 0; j < 4; j++)
                lds64(bfr[j], slot + 4096u + (uint32_t)(wn * 4 + j) * 256u + l8);
            #pragma unroll
            for (int i = 0; i < 4; i++) {
                uint32_t a[4];
                lds128(a, slot + (uint32_t)(wm * 4 + i) * 512u + l16);
                #pragma unroll
                for (int j = 0; j < 4; j++)
                    mma16(acc[i][j], a, bfr[j][0], bfr[j][1]);
            }

            if (s + 3 < 32) {
                load_AB(sb + OFF_ST + (uint32_t)((s + 3) & 3) * STG, s + 3, mi0, ni0, t);
                CP_COMMIT();
            }
        }
        __syncthreads();

        // prefetch next phase / epilogue W while spilling
        if (ph == 0) {
            load_AB(sb + OFF_ST + 0u * STG, 0, mi0, nib + 16, t); CP_COMMIT();
            load_AB(sb + OFF_ST + 1u * STG, 1, mi0, nib + 16, t); CP_COMMIT();
            load_AB(sb + OFF_ST + 2u * STG, 2, mi0, nib + 16, t); CP_COMMIT();
        } else {
            load_Wc(sb, 0, 0, w, lane); CP_COMMIT();
            load_Wc(sb, 1, 1, w, lane); CP_COMMIT();
        }

        // ---- spill o' (fp16 frags, 1/512 folded): row = kf2p + (m>>5)*64
        //      within-row byte = (j8*4 + r)*8 + (j&1)*4, j8 = ph*4 + wn
        #pragma unroll
        for (int i = 0; i < 4; i++)
            #pragma unroll
            for (int j = 0; j < 4; j++)
                #pragma unroll
                for (int ccp = 0; ccp < 2; ccp++) {
                    int m = wm * 64 + i * 16 + g + ccp * 8;
                    int row = (m & 31) * 2 + (j >> 1) + (m >> 5) * 64;
                    int addr = row * 264 + ((ph * 4 + wn) * 4 + r) * 8 + (j & 1) * 4;
                    sts32(sb + (uint32_t)addr,
                          pack_h2(acc[i][j][ccp * 2] * sc, acc[i][j][ccp * 2 + 1] * sc));
                }
        __syncthreads();
    }

    // ---- epilogue: z[zz][pair] = W * o' (K=1024, 16 chunks of k'=64, 32 pairs)
    // warp w: zz rows w*16..+15 (zg = w), all 4 pf (i-local) tiles.
    float zacc[4][4];
    #pragma unroll
    for (int pf = 0; pf < 4; pf++)
        #pragma unroll
        for (int cc = 0; cc < 4; cc++) zacc[pf][cc] = 0.0f;

    for (int ch = 0; ch < 16; ch++) {
        int buf = ch & 1;
        if (ch < 15) CP_WAIT1(); else CP_WAIT0();
        __syncwarp();

        uint32_t wsb = sb + OFF_ST + (uint32_t)w * 4096u + (buf ? 2048u : 0u);
        #pragma unroll
        for (int ks = 0; ks < 4; ks++) {
            uint32_t aw[4];
            lds128(aw, wsb + (uint32_t)(ks * 512) + l16);
            uint32_t bfr[4][2];
            #pragma unroll
            for (int pf = 0; pf < 4; pf++)
                lds64(bfr[pf], sb + (uint32_t)(((ch * 4 + ks) + pf * 64) * 264) + l8);
            #pragma unroll
            for (int pf = 0; pf < 4; pf++)
                mma16(zacc[pf], aw, bfr[pf][0], bfr[pf][1]);
        }
        if (ch + 2 < 16) { load_Wc(sb, ch + 2, buf, w, lane); CP_COMMIT(); }
    }

    // ---- write z (+bias): n-output = j8 = 2r + (cc&1); ig = by*4 + pf
    float bf0 = b_final[w * 16 + g];
    float bf1 = b_final[w * 16 + g + 8];
    #pragma unroll
    for (int pf = 0; pf < 4; pf++)
        #pragma unroll
        for (int cc = 0; cc < 4; cc++) {
            int zz = w * 16 + g + ((cc & 2) ? 8 : 0);
            int jg = blockIdx.x * 8 + 2 * r + (cc & 1);
            int ig = blockIdx.y * 4 + pf;
            z[((size_t)(ig * S_DIM + jg)) * 128 + zz] =
                zacc[pf][cc] + ((cc & 2) ? bf1 : bf0);
        }
}

// ---------------------------------------------------------------- launch
extern "C" void kernel_launch(void* const* d_in, const int* in_sizes, int n_in,
                              void* d_out, int out_size)
{
    const float* m_si    = (const float*)d_in[0];
    const float* ln_g    = (const float*)d_in[1];
    const float* ln_b    = (const float*)d_in[2];
    const float* w_ab    = (const float*)d_in[3];
    const float* w_final = (const float*)d_in[4];
    const float* b_final = (const float*)d_in[5];
    float* z = (float*)d_out;
    (void)in_sizes; (void)n_in; (void)out_size;

    ln_proj_kernel<<<3072, 256>>>(m_si, ln_g, ln_b, w_ab, w_final);

    cudaFuncSetAttribute(opm_mma_kernel,
                         cudaFuncAttributeMaxDynamicSharedMemorySize, SMEM2);
    dim3 grid(48, 96);   // (8-j tiles, 4-i tiles)
    opm_mma_kernel<<<grid, 256, SMEM2>>>(b_final, z);
}